// round 7
// baseline (speedup 1.0000x reference)
#include <cuda_runtime.h>
#include <cuda_bf16.h>
#include <math.h>

typedef unsigned long long ull;

#define N_TOT 262144
#define GS    64
#define NGRP  (N_TOT / GS)
#define PAD   68
#define HST   132
#define WST   72
#define WSTA  136

// ---------------- device scratch (no allocations allowed) ----------------
__device__ ull   g_keys[2][N_TOT];
__device__ int   g_ind1[N_TOT];
__device__ int   g_ind2[N_TOT];
__device__ int   g_inv1[N_TOT];
__device__ int   g_ind12[N_TOT];
__device__ float g_x1[(size_t)N_TOT * 64];

// ---------------- Hilbert encode (Skilling), order = 10 ----------------
__device__ __forceinline__ unsigned hilbert3(unsigned X0, unsigned X1, unsigned X2)
{
    const int order = 10;
    for (unsigned Q = 1u << (order - 1); Q > 1; Q >>= 1) {
        unsigned P = Q - 1;
        if (X0 & Q) X0 ^= P;
        unsigned t = (X0 ^ X1) & P;
        if (X1 & Q) { X0 ^= P; } else { X0 ^= t; X1 ^= t; }
        t = (X0 ^ X2) & P;
        if (X2 & Q) { X0 ^= P; } else { X0 ^= t; X2 ^= t; }
    }
    X1 ^= X0;
    X2 ^= X1;
    unsigned t = 0;
    for (unsigned Q = 1u << (order - 1); Q > 1; Q >>= 1)
        if (X2 & Q) t ^= (Q - 1);
    X0 ^= t; X1 ^= t; X2 ^= t;
    unsigned code = 0;
#pragma unroll
    for (int b = order - 1; b >= 0; b--) {
        code = (code << 3) | (((X0 >> b) & 1u) << 2) | (((X1 >> b) & 1u) << 1) | ((X2 >> b) & 1u);
    }
    return code;
}

__global__ void __launch_bounds__(256) codes_kernel(const int* __restrict__ vox_coors)
{
    int i = blockIdx.x * 256 + threadIdx.x;
    if (i >= N_TOT) return;
    int4 v = ((const int4*)vox_coors)[i];
    unsigned b  = (unsigned)v.x;
    unsigned c1 = hilbert3((unsigned)v.y, (unsigned)v.z,      (unsigned)v.w);
    unsigned c2 = hilbert3((unsigned)v.y, (unsigned)v.z + 1u, (unsigned)v.w + 1u);
    // Reference computes keys in int32 (JAX x64 disabled): batch<<30 overflows the
    // sign bit, so signed ascending order = unsigned ascending order of (key ^ 0x80000000).
    unsigned k1 = (((b << 30) | c1) ^ 0x80000000u);
    unsigned k2 = (((b << 30) | c2) ^ 0x80000000u);
    g_keys[0][i] = (((ull)k1) << 32) | (unsigned)i;
    g_keys[1][i] = (((ull)k2) << 32) | (unsigned)i;
}

// ---------------- bitonic sort (uint64 ascending, N = 2^18) ----------------
__global__ void __launch_bounds__(1024) bitonic_local_sort()
{
    __shared__ ull s[4096];
    ull* arr = g_keys[blockIdx.y];
    int base = blockIdx.x * 4096;
    int tid = threadIdx.x;
#pragma unroll
    for (int e = 0; e < 4; e++) s[e * 1024 + tid] = arr[base + e * 1024 + tid];
    __syncthreads();
    for (int k = 2; k <= 4096; k <<= 1) {
        for (int j = k >> 1; j >= 1; j >>= 1) {
#pragma unroll
            for (int e = 0; e < 2; e++) {
                int v = e * 1024 + tid;
                int i = ((v & ~(j - 1)) << 1) | (v & (j - 1));
                int l = i | j;
                bool up = (((unsigned)(base + i)) & (unsigned)k) == 0;
                ull A = s[i], B = s[l];
                if ((A > B) == up) { s[i] = B; s[l] = A; }
            }
            __syncthreads();
        }
    }
#pragma unroll
    for (int e = 0; e < 4; e++) arr[base + e * 1024 + tid] = s[e * 1024 + tid];
}

__global__ void __launch_bounds__(1024) bitonic_local_merge(int k)
{
    __shared__ ull s[4096];
    ull* arr = g_keys[blockIdx.y];
    int base = blockIdx.x * 4096;
    int tid = threadIdx.x;
#pragma unroll
    for (int e = 0; e < 4; e++) s[e * 1024 + tid] = arr[base + e * 1024 + tid];
    __syncthreads();
    bool up = (((unsigned)base) & (unsigned)k) == 0;  // k > 4096 -> constant per chunk
    for (int j = 2048; j >= 1; j >>= 1) {
#pragma unroll
        for (int e = 0; e < 2; e++) {
            int v = e * 1024 + tid;
            int i = ((v & ~(j - 1)) << 1) | (v & (j - 1));
            int l = i | j;
            ull A = s[i], B = s[l];
            if ((A > B) == up) { s[i] = B; s[l] = A; }
        }
        __syncthreads();
    }
#pragma unroll
    for (int e = 0; e < 4; e++) arr[base + e * 1024 + tid] = s[e * 1024 + tid];
}

__global__ void __launch_bounds__(256) bitonic_global(int k, int j)
{
    ull* arr = g_keys[blockIdx.y];
    int v = blockIdx.x * 256 + threadIdx.x;   // 0 .. N/2-1
    int i = ((v & ~(j - 1)) << 1) | (v & (j - 1));
    int l = i | j;
    bool up = (((unsigned)i) & (unsigned)k) == 0;
    ull A = arr[i], B = arr[l];
    if ((A > B) == up) { arr[i] = B; arr[l] = A; }
}

__global__ void __launch_bounds__(256) extract_kernel()
{
    int i = blockIdx.x * 256 + threadIdx.x;
    int i1 = (int)(g_keys[0][i] & 0xffffffffull);
    int i2 = (int)(g_keys[1][i] & 0xffffffffull);
    g_ind1[i] = i1;
    g_ind2[i] = i2;
    g_inv1[i1] = i;
}

__global__ void __launch_bounds__(256) ind12_kernel()
{
    int i = blockIdx.x * 256 + threadIdx.x;
    g_ind12[i] = g_inv1[g_ind2[i]];
}

// ---------------- tf32 helpers ----------------
__device__ __forceinline__ float tf32r(float x)
{
    unsigned u;
    asm("cvt.rna.tf32.f32 %0, %1;" : "=r"(u) : "f"(x));
    return __uint_as_float(u);
}

// m16n8k4 tf32 mma: D += A(16x4) * B(4x8).
// A: a0=(row g, col t), a1=(row g+8, col t); B: b0=(k t, col g);
// D: c0=(g,2t) c1=(g,2t+1) c2=(g+8,2t) c3=(g+8,2t+1).  (g=lane>>2, t=lane&3)
__device__ __forceinline__ void mma4(float4& d, float a0, float a1, float b0)
{
    asm volatile("mma.sync.aligned.m16n8k4.row.col.f32.tf32.tf32.f32 "
                 "{%0,%1,%2,%3}, {%4,%5}, {%6}, {%0,%1,%2,%3};"
                 : "+f"(d.x), "+f"(d.y), "+f"(d.z), "+f"(d.w)
                 : "r"(__float_as_uint(a0)), "r"(__float_as_uint(a1)),
                   "r"(__float_as_uint(b0)));
}

__device__ __forceinline__ void load_afrag(const float* A, int stride, int mrow,
                                           int gid, int tig, int koff,
                                           float* a0, float* a1)
{
#pragma unroll
    for (int ks = 0; ks < 16; ks++) {
        a0[ks] = A[(mrow + gid) * stride + koff + 4 * ks + tig];
        a1[ks] = A[(mrow + gid + 8) * stride + koff + 4 * ks + tig];
    }
}

__device__ __forceinline__ float gelu_tanh(float x)
{
    float x3 = x * x * x;
    float t = tanhf(0.7978845608028654f * (x + 0.044715f * x3));
    return 0.5f * x * (1.0f + t);
}

// layernorm rows of sx[64][PAD] -> row-major tf32-rounded sxn[64][PAD] (16 warps, 4 rows each)
__device__ __forceinline__ void ln_rows(const float* sx, float* sxn, int tid)
{
    int lane = tid & 31, w = tid >> 5;
#pragma unroll
    for (int rr = 0; rr < 4; rr++) {
        int r = w * 4 + rr;
        float a = sx[r * PAD + lane];
        float b = sx[r * PAD + lane + 32];
        float s = a + b, q = a * a + b * b;
#pragma unroll
        for (int m = 16; m; m >>= 1) {
            s += __shfl_xor_sync(0xffffffffu, s, m);
            q += __shfl_xor_sync(0xffffffffu, q, m);
        }
        float mean = s * (1.0f / 64.0f);
        float rs = rsqrtf(q * (1.0f / 64.0f) - mean * mean + 1e-5f);
        sxn[r * PAD + lane]      = tf32r((a - mean) * rs);
        sxn[r * PAD + lane + 32] = tf32r((b - mean) * rs);
    }
}

// smem: sx 64*68 | sxn 64*68 | sqkT 128*68 | sv 64*68 | sattT 256*68 | sh 64*132 | wbuf 9216
#define SMEM_FLOATS (64*PAD + 64*PAD + 128*PAD + 64*PAD + 256*PAD + 64*HST + 9216)
#define SMEM_BYTES  (SMEM_FLOATS * 4)

__global__ void __launch_bounds__(512, 1) layer_kernel(
    int layer,
    const float* __restrict__ feats_in, const float* __restrict__ pts,
    const float* __restrict__ wpos, const float* __restrict__ wqkv,
    const float* __restrict__ wo,   const float* __restrict__ wffa,
    const float* __restrict__ wffb, float* __restrict__ dst_out)
{
    extern __shared__ float smf[];
    float* sx    = smf;                    // [64][PAD] residual stream (fp32)
    float* sxn   = sx    + 64 * PAD;       // [64][PAD] ln out (tf32) / o (tf32)
    float* sqkT  = sxn   + 64 * PAD;       // [128][PAD] qT rows 0..63, kT rows 64..127
    float* sv    = sqkT  + 128 * PAD;      // [64][PAD]  v row-major
    float* sattT = sv    + 64 * PAD;       // [256][PAD] att (4 heads, key-major)
    float* sh    = sattT + 256 * PAD;      // [64][HST]  ff hidden half (tf32)
    float* wbuf  = sh    + 64 * HST;       // 9216 floats, staged weights (tf32)

    const float* feats = layer ? g_x1   : feats_in;
    float*       dst   = layer ? dst_out : g_x1;
    const int*   gIdx  = layer ? g_ind12 : g_ind1;
    const int*   pIdx  = layer ? g_ind2  : g_ind1;

    int tid = threadIdx.x;
    int g = blockIdx.x;
    int lane = tid & 31, w = tid >> 5;            // 16 warps
    int gid = lane >> 2, tig = lane & 3;
    int mrow = 16 * (w & 3), cg = w >> 2;         // 4 M-tiles x 4 N-col-groups
    int t256 = tid & 255;
    int tr = t256 >> 4, tc = t256 & 15;
    int hhalf = tid >> 8;                         // 0/1: heads {0,1} / {2,3}

    float a0[16], a1[16];

    // stage w_pos (4x64, fp32)
    if (tid < 256) wbuf[tid] = wpos[tid];
    __syncthreads();

    // ---- P0: x = feats[gIdx] + p @ w_pos ----
    {
        int r = tid >> 3;
        int cs = (tid & 7) * 8;
        int gi = gIdx[g * GS + r];
        int pi = pIdx[g * GS + r];
        float4 p = *(const float4*)(pts + (size_t)pi * 4);
#pragma unroll
        for (int cc = 0; cc < 8; cc += 4) {
            int c = cs + cc;
            float4 f  = *(const float4*)(feats + (size_t)gi * 64 + c);
            float4 w0 = *(const float4*)(wbuf + c);
            float4 w1 = *(const float4*)(wbuf + 64 + c);
            float4 w2 = *(const float4*)(wbuf + 128 + c);
            float4 w3 = *(const float4*)(wbuf + 192 + c);
            f.x += p.x * w0.x + p.y * w1.x + p.z * w2.x + p.w * w3.x;
            f.y += p.x * w0.y + p.y * w1.y + p.z * w2.y + p.w * w3.y;
            f.z += p.x * w0.z + p.y * w1.z + p.z * w2.z + p.w * w3.z;
            f.w += p.x * w0.w + p.y * w1.w + p.z * w2.w + p.w * w3.w;
            *(float4*)(sx + r * PAD + c) = f;
        }
    }
    __syncthreads();

    // ---- P1: layernorm -> xn (row-major, tf32) ----
    ln_rows(sx, sxn, tid);
    __syncthreads();

    // ---- P2: q/k/v GEMMs via tf32 mma, weights staged in thirds ----
    load_afrag(sxn, PAD, mrow, gid, tig, 0, a0, a1);
#pragma unroll 1
    for (int s = 0; s < 3; s++) {
        for (int i = tid; i < 4096; i += 512)
            wbuf[(i >> 6) * WST + (i & 63)] = tf32r(wqkv[(i >> 6) * 192 + s * 64 + (i & 63)]);
        __syncthreads();
#pragma unroll
        for (int t = 0; t < 2; t++) {
            int nb = (cg * 2 + t) * 8;
            float4 acc = make_float4(0.f, 0.f, 0.f, 0.f);
#pragma unroll
            for (int ks = 0; ks < 16; ks++)
                mma4(acc, a0[ks], a1[ks], wbuf[(4 * ks + tig) * WST + nb + gid]);
            int n0 = nb + 2 * tig, r0 = mrow + gid;
            if (s < 2) {   // q, k stored transposed for SIMT attention
                int ro = s * 64;
                sqkT[(ro + n0) * PAD + r0]         = acc.x;
                sqkT[(ro + n0 + 1) * PAD + r0]     = acc.y;
                sqkT[(ro + n0) * PAD + r0 + 8]     = acc.z;
                sqkT[(ro + n0 + 1) * PAD + r0 + 8] = acc.w;
            } else {       // v row-major
                *(float2*)(sv + r0 * PAD + n0)       = make_float2(acc.x, acc.y);
                *(float2*)(sv + (r0 + 8) * PAD + n0) = make_float2(acc.z, acc.w);
            }
        }
        __syncthreads();
    }

    // stage w_o (64x64) — consumed in P3c; P3a/P3b syncs cover visibility
    for (int i = tid; i < 4096; i += 512)
        wbuf[(i >> 6) * WST + (i & 63)] = tf32r(wo[i]);

    // ---- P3a: scores + softmax -> sattT (SIMT fp32, 2 heads per 256-thread half) ----
#pragma unroll 1
    for (int hi = 0; hi < 2; hi++) {
        int h = hhalf * 2 + hi;
        float s[4][4];
#pragma unroll
        for (int i = 0; i < 4; i++)
#pragma unroll
            for (int j = 0; j < 4; j++) s[i][j] = 0.0f;
#pragma unroll 4
        for (int d = 0; d < 16; d++) {
            float4 af = *(float4*)(sqkT + (16 * h + d) * PAD + 4 * tr);
            float4 bf = *(float4*)(sqkT + (64 + 16 * h + d) * PAD + 4 * tc);
            float av[4] = {af.x, af.y, af.z, af.w};
            float bv[4] = {bf.x, bf.y, bf.z, bf.w};
#pragma unroll
            for (int i = 0; i < 4; i++)
#pragma unroll
                for (int j = 0; j < 4; j++) s[i][j] += av[i] * bv[j];
        }
        float inv[4];
#pragma unroll
        for (int i = 0; i < 4; i++) {
            float sum = 0.0f;
#pragma unroll
            for (int j = 0; j < 4; j++) { s[i][j] = __expf(s[i][j] * 0.25f); sum += s[i][j]; }
#pragma unroll
            for (int msk = 1; msk < 16; msk <<= 1) sum += __shfl_xor_sync(0xffffffffu, sum, msk);
            inv[i] = 1.0f / sum;
        }
#pragma unroll
        for (int j = 0; j < 4; j++) {
            *(float4*)(sattT + (h * 64 + 4 * tc + j) * PAD + 4 * tr) =
                make_float4(s[0][j] * inv[0], s[1][j] * inv[1], s[2][j] * inv[2], s[3][j] * inv[3]);
        }
    }
    __syncthreads();

    // ---- P3b: o = att @ v, 4 heads x 128 threads; store o row-major tf32 into sxn ----
    {
        int hh = tid >> 7, u = tid & 127;
        int otr = u >> 3, otc = u & 7;            // 4 q-rows x 2 dims per thread
        float o[4][2];
#pragma unroll
        for (int i = 0; i < 4; i++) { o[i][0] = 0.0f; o[i][1] = 0.0f; }
#pragma unroll 4
        for (int key = 0; key < 64; key++) {
            float4 af = *(float4*)(sattT + (hh * 64 + key) * PAD + 4 * otr);
            float2 bf = *(float2*)(sv + key * PAD + 16 * hh + 2 * otc);
            float av[4] = {af.x, af.y, af.z, af.w};
#pragma unroll
            for (int i = 0; i < 4; i++) {
                o[i][0] += av[i] * bf.x;
                o[i][1] += av[i] * bf.y;
            }
        }
#pragma unroll
        for (int i = 0; i < 4; i++) {
            *(float2*)(sxn + (4 * otr + i) * PAD + 16 * hh + 2 * otc) =
                make_float2(tf32r(o[i][0]), tf32r(o[i][1]));
        }
    }
    __syncthreads();

    // ---- P3c: x += o @ w_o (tf32 mma) ----
    load_afrag(sxn, PAD, mrow, gid, tig, 0, a0, a1);
#pragma unroll
    for (int t = 0; t < 2; t++) {
        int nb = (cg * 2 + t) * 8;
        float4 acc = make_float4(0.f, 0.f, 0.f, 0.f);
#pragma unroll
        for (int ks = 0; ks < 16; ks++)
            mma4(acc, a0[ks], a1[ks], wbuf[(4 * ks + tig) * WST + nb + gid]);
        int n0 = nb + 2 * tig, r0 = mrow + gid;
        sx[r0 * PAD + n0]           += acc.x;
        sx[r0 * PAD + n0 + 1]       += acc.y;
        sx[(r0 + 8) * PAD + n0]     += acc.z;
        sx[(r0 + 8) * PAD + n0 + 1] += acc.w;
    }
    __syncthreads();

    // ---- P4: FF. ln -> xn; ffa/ffb in halves, ffb accum in registers ----
    ln_rows(sx, sxn, tid);
    float4 accB[2];
    accB[0] = make_float4(0.f, 0.f, 0.f, 0.f);
    accB[1] = make_float4(0.f, 0.f, 0.f, 0.f);

#pragma unroll 1
    for (int half = 0; half < 2; half++) {
        __syncthreads();   // xn ready (half 0) / prev ffb done reading wbuf (half 1)
        for (int i = tid; i < 8192; i += 512)
            wbuf[(i >> 7) * WSTA + (i & 127)] =
                tf32r(wffa[(i >> 7) * 256 + half * 128 + (i & 127)]);
        __syncthreads();

        // ffa half: h = gelu(xn @ wffa[:, half]) (tf32 out)
        load_afrag(sxn, PAD, mrow, gid, tig, 0, a0, a1);
#pragma unroll
        for (int t = 0; t < 4; t++) {
            int nb = (cg * 4 + t) * 8;
            float4 acc = make_float4(0.f, 0.f, 0.f, 0.f);
#pragma unroll
            for (int ks = 0; ks < 16; ks++)
                mma4(acc, a0[ks], a1[ks], wbuf[(4 * ks + tig) * WSTA + nb + gid]);
            int n0 = nb + 2 * tig, r0 = mrow + gid;
            *(float2*)(sh + r0 * HST + n0) =
                make_float2(tf32r(gelu_tanh(acc.x)), tf32r(gelu_tanh(acc.y)));
            *(float2*)(sh + (r0 + 8) * HST + n0) =
                make_float2(tf32r(gelu_tanh(acc.z)), tf32r(gelu_tanh(acc.w)));
        }
        __syncthreads();

        // stage wffb rows [half*128, half*128+128)
        for (int i = tid; i < 8192; i += 512)
            wbuf[(i >> 6) * WST + (i & 63)] =
                tf32r(wffb[(half * 128 + (i >> 6)) * 64 + (i & 63)]);
        __syncthreads();

        // ffb: accB += h @ wffb_half  (K=128 per half, 2 chunks of 16 k4-steps)
#pragma unroll 1
        for (int c = 0; c < 2; c++) {
            load_afrag(sh, HST, mrow, gid, tig, 64 * c, a0, a1);
#pragma unroll
            for (int t = 0; t < 2; t++) {
                int nb = (cg * 2 + t) * 8;
#pragma unroll
                for (int ks = 0; ks < 16; ks++)
                    mma4(accB[t], a0[ks], a1[ks],
                         wbuf[(4 * (16 * c + ks) + tig) * WST + nb + gid]);
            }
        }
    }

    // ---- write out: dst = x + ff ----
#pragma unroll
    for (int t = 0; t < 2; t++) {
        int nb = (cg * 2 + t) * 8, n0 = nb + 2 * tig, r0 = mrow + gid;
        float2 lo = make_float2(sx[r0 * PAD + n0] + accB[t].x,
                                sx[r0 * PAD + n0 + 1] + accB[t].y);
        float2 hi = make_float2(sx[(r0 + 8) * PAD + n0] + accB[t].z,
                                sx[(r0 + 8) * PAD + n0 + 1] + accB[t].w);
        *(float2*)(dst + (size_t)(g * GS + r0) * 64 + n0)     = lo;
        *(float2*)(dst + (size_t)(g * GS + r0 + 8) * 64 + n0) = hi;
    }
}

// ---------------- launch ----------------
extern "C" void kernel_launch(void* const* d_in, const int* in_sizes, int n_in,
                              void* d_out, int out_size)
{
    const float* vox_feats = (const float*)d_in[0];
    const float* pts_coors = (const float*)d_in[1];
    const int*   vox_coors = (const int*)d_in[2];
    const float* w[10];
    for (int i = 0; i < 10; i++) w[i] = (const float*)d_in[n_in - 10 + i];
    float* out = (float*)d_out;

    cudaFuncSetAttribute(layer_kernel, cudaFuncAttributeMaxDynamicSharedMemorySize, SMEM_BYTES);

    codes_kernel<<<N_TOT / 256, 256>>>(vox_coors);

    dim3 gl(64, 2);
    bitonic_local_sort<<<gl, 1024>>>();
    for (int k = 8192; k <= N_TOT; k <<= 1) {
        for (int j = k >> 1; j >= 4096; j >>= 1)
            bitonic_global<<<dim3(512, 2), 256>>>(k, j);
        bitonic_local_merge<<<gl, 1024>>>(k);
    }

    extract_kernel<<<N_TOT / 256, 256>>>();
    ind12_kernel<<<N_TOT / 256, 256>>>();

    layer_kernel<<<NGRP, 512, SMEM_BYTES>>>(0, vox_feats, pts_coors,
                                            w[0], w[1], w[2], w[3], w[4], out);
    layer_kernel<<<NGRP, 512, SMEM_BYTES>>>(1, vox_feats, pts_coors,
                                            w[5], w[6], w[7], w[8], w[9], out);
}

// round 9
// speedup vs baseline: 1.4166x; 1.4166x over previous
#include <cuda_runtime.h>
#include <cuda_bf16.h>
#include <math.h>

typedef unsigned long long ull;

#define N_TOT 262144
#define GS    64
#define NGRP  (N_TOT / GS)

#define PAD 68   // sxn / satt / sh stride (afrag-friendly: ≡4 mod 32)
#define SXS 66   // sx stride (float2-only access)
#define KVS 72   // skT / sv / wbuf stride (B-operand friendly: ≡8 mod 32)

// ---------------- device scratch (no allocations allowed) ----------------
__device__ ull   g_keys[2][N_TOT];
__device__ int   g_ind1[N_TOT];
__device__ int   g_ind2[N_TOT];
__device__ int   g_inv1[N_TOT];
__device__ int   g_ind12[N_TOT];
__device__ float g_x1[(size_t)N_TOT * 64];

// ---------------- Hilbert encode (Skilling), order = 10 ----------------
__device__ __forceinline__ unsigned hilbert3(unsigned X0, unsigned X1, unsigned X2)
{
    const int order = 10;
    for (unsigned Q = 1u << (order - 1); Q > 1; Q >>= 1) {
        unsigned P = Q - 1;
        if (X0 & Q) X0 ^= P;
        unsigned t = (X0 ^ X1) & P;
        if (X1 & Q) { X0 ^= P; } else { X0 ^= t; X1 ^= t; }
        t = (X0 ^ X2) & P;
        if (X2 & Q) { X0 ^= P; } else { X0 ^= t; X2 ^= t; }
    }
    X1 ^= X0;
    X2 ^= X1;
    unsigned t = 0;
    for (unsigned Q = 1u << (order - 1); Q > 1; Q >>= 1)
        if (X2 & Q) t ^= (Q - 1);
    X0 ^= t; X1 ^= t; X2 ^= t;
    unsigned code = 0;
#pragma unroll
    for (int b = order - 1; b >= 0; b--) {
        code = (code << 3) | (((X0 >> b) & 1u) << 2) | (((X1 >> b) & 1u) << 1) | ((X2 >> b) & 1u);
    }
    return code;
}

__global__ void __launch_bounds__(256) codes_kernel(const int* __restrict__ vox_coors)
{
    int i = blockIdx.x * 256 + threadIdx.x;
    if (i >= N_TOT) return;
    int4 v = ((const int4*)vox_coors)[i];
    unsigned b  = (unsigned)v.x;
    unsigned c1 = hilbert3((unsigned)v.y, (unsigned)v.z,      (unsigned)v.w);
    unsigned c2 = hilbert3((unsigned)v.y, (unsigned)v.z + 1u, (unsigned)v.w + 1u);
    // Reference computes keys in int32 (JAX x64 disabled): batch<<30 overflows the
    // sign bit; signed ascending == unsigned ascending of (key ^ 0x80000000).
    unsigned k1 = (((b << 30) | c1) ^ 0x80000000u);
    unsigned k2 = (((b << 30) | c2) ^ 0x80000000u);
    g_keys[0][i] = (((ull)k1) << 32) | (unsigned)i;
    g_keys[1][i] = (((ull)k2) << 32) | (unsigned)i;
}

// ---------------- bitonic sort (uint64 ascending, N = 2^18) ----------------
__global__ void __launch_bounds__(1024) bitonic_local_sort()
{
    __shared__ ull s[4096];
    ull* arr = g_keys[blockIdx.y];
    int base = blockIdx.x * 4096;
    int tid = threadIdx.x;
#pragma unroll
    for (int e = 0; e < 4; e++) s[e * 1024 + tid] = arr[base + e * 1024 + tid];
    __syncthreads();
    for (int k = 2; k <= 4096; k <<= 1) {
        for (int j = k >> 1; j >= 1; j >>= 1) {
#pragma unroll
            for (int e = 0; e < 2; e++) {
                int v = e * 1024 + tid;
                int i = ((v & ~(j - 1)) << 1) | (v & (j - 1));
                int l = i | j;
                bool up = (((unsigned)(base + i)) & (unsigned)k) == 0;
                ull A = s[i], B = s[l];
                if ((A > B) == up) { s[i] = B; s[l] = A; }
            }
            __syncthreads();
        }
    }
#pragma unroll
    for (int e = 0; e < 4; e++) arr[base + e * 1024 + tid] = s[e * 1024 + tid];
}

__global__ void __launch_bounds__(1024) bitonic_local_merge(int k)
{
    __shared__ ull s[4096];
    ull* arr = g_keys[blockIdx.y];
    int base = blockIdx.x * 4096;
    int tid = threadIdx.x;
#pragma unroll
    for (int e = 0; e < 4; e++) s[e * 1024 + tid] = arr[base + e * 1024 + tid];
    __syncthreads();
    bool up = (((unsigned)base) & (unsigned)k) == 0;
    for (int j = 2048; j >= 1; j >>= 1) {
#pragma unroll
        for (int e = 0; e < 2; e++) {
            int v = e * 1024 + tid;
            int i = ((v & ~(j - 1)) << 1) | (v & (j - 1));
            int l = i | j;
            ull A = s[i], B = s[l];
            if ((A > B) == up) { s[i] = B; s[l] = A; }
        }
        __syncthreads();
    }
#pragma unroll
    for (int e = 0; e < 4; e++) arr[base + e * 1024 + tid] = s[e * 1024 + tid];
}

__global__ void __launch_bounds__(256) bitonic_global(int k, int j)
{
    ull* arr = g_keys[blockIdx.y];
    int v = blockIdx.x * 256 + threadIdx.x;
    int i = ((v & ~(j - 1)) << 1) | (v & (j - 1));
    int l = i | j;
    bool up = (((unsigned)i) & (unsigned)k) == 0;
    ull A = arr[i], B = arr[l];
    if ((A > B) == up) { arr[i] = B; arr[l] = A; }
}

__global__ void __launch_bounds__(256) extract_kernel()
{
    int i = blockIdx.x * 256 + threadIdx.x;
    int i1 = (int)(g_keys[0][i] & 0xffffffffull);
    int i2 = (int)(g_keys[1][i] & 0xffffffffull);
    g_ind1[i] = i1;
    g_ind2[i] = i2;
    g_inv1[i1] = i;
}

__global__ void __launch_bounds__(256) ind12_kernel()
{
    int i = blockIdx.x * 256 + threadIdx.x;
    g_ind12[i] = g_inv1[g_ind2[i]];
}

// ---------------- tf32 helpers ----------------
__device__ __forceinline__ float tf32r(float x)
{
    unsigned u;
    asm("cvt.rna.tf32.f32 %0, %1;" : "=r"(u) : "f"(x));
    return __uint_as_float(u);
}

// m16n8k4 tf32 mma: D += A(16x4) * B(4x8).
// A: a0=(row g, col t), a1=(row g+8, col t); B: b0=(k t, col g);
// D: c0=(g,2t) c1=(g,2t+1) c2=(g+8,2t) c3=(g+8,2t+1).  (g=lane>>2, t=lane&3)
__device__ __forceinline__ void mma4(float4& d, float a0, float a1, float b0)
{
    asm volatile("mma.sync.aligned.m16n8k4.row.col.f32.tf32.tf32.f32 "
                 "{%0,%1,%2,%3}, {%4,%5}, {%6}, {%0,%1,%2,%3};"
                 : "+f"(d.x), "+f"(d.y), "+f"(d.z), "+f"(d.w)
                 : "r"(__float_as_uint(a0)), "r"(__float_as_uint(a1)),
                   "r"(__float_as_uint(b0)));
}

__device__ __forceinline__ void load_afrag(const float* A, int stride, int mrow,
                                           int gid, int tig, float* a0, float* a1)
{
#pragma unroll
    for (int ks = 0; ks < 16; ks++) {
        a0[ks] = A[(mrow + gid) * stride + 4 * ks + tig];
        a1[ks] = A[(mrow + gid + 8) * stride + 4 * ks + tig];
    }
}

__device__ __forceinline__ float gelu_tanh(float x)
{
    float x3 = x * x * x;
    float t = tanhf(0.7978845608028654f * (x + 0.044715f * x3));
    return 0.5f * x * (1.0f + t);
}

// layernorm rows: sx[64][SXS] -> tf32 sxn[64][PAD]  (8 warps x 8 rows)
__device__ __forceinline__ void ln_rows(const float* sx, float* sxn, int tid)
{
    int lane = tid & 31, w = tid >> 5;
#pragma unroll
    for (int rr = 0; rr < 8; rr++) {
        int r = w * 8 + rr;
        float a = sx[r * SXS + lane];
        float b = sx[r * SXS + lane + 32];
        float s = a + b, q = a * a + b * b;
#pragma unroll
        for (int m = 16; m; m >>= 1) {
            s += __shfl_xor_sync(0xffffffffu, s, m);
            q += __shfl_xor_sync(0xffffffffu, q, m);
        }
        float mean = s * (1.0f / 64.0f);
        float rs = rsqrtf(q * (1.0f / 64.0f) - mean * mean + 1e-5f);
        sxn[r * PAD + lane]      = tf32r((a - mean) * rs);
        sxn[r * PAD + lane + 32] = tf32r((b - mean) * rs);
    }
}

// smem: sx 64*66 | sxn 64*68 | skT 64*72 | sv 64*72 | satt 128*68 (alias sh) | wbuf 32*72
#define SMEM_FLOATS (64*SXS + 64*PAD + 64*KVS + 64*KVS + 128*PAD + 32*KVS)
#define SMEM_BYTES  (SMEM_FLOATS * 4)   // 115200 B -> 2 blocks/SM

__global__ void __launch_bounds__(256, 2) layer_kernel(
    int layer,
    const float* __restrict__ feats_in, const float* __restrict__ pts,
    const float* __restrict__ wpos, const float* __restrict__ wqkv,
    const float* __restrict__ wo,   const float* __restrict__ wffa,
    const float* __restrict__ wffb, float* __restrict__ dst_out)
{
    extern __shared__ float smf[];
    float* sx   = smf;                  // [64][66] fp32 residual
    float* sxn  = sx   + 64 * SXS;      // [64][68] tf32 ln-out -> q -> o -> ln2
    float* skT  = sxn  + 64 * PAD;      // [64][72] k transposed [dim][key]
    float* sv   = skT  + 64 * KVS;      // [64][72] v row-major [key][dim]
    float* satt = sv   + 64 * KVS;      // [128][68] att (2 heads) / sh [64][68]
    float* sh   = satt;
    float* wbuf = satt + 128 * PAD;     // [32][72] weight chunk (tf32)

    const float* feats = layer ? g_x1   : feats_in;
    float*       dst   = layer ? dst_out : g_x1;
    const int*   gIdx  = layer ? g_ind12 : g_ind1;
    const int*   pIdx  = layer ? g_ind2  : g_ind1;

    int tid = threadIdx.x;
    int g = blockIdx.x;
    int lane = tid & 31, w = tid >> 5;
    int gid = lane >> 2, tig = lane & 3;
    int mrow = 16 * (w & 3), wsel = w >> 2;     // 4 M-tiles x 2 cg-phases

    float a0[16], a1[16];

    // ---- P0: stage wpos; x = feats[gIdx] + p @ wpos ----
    wbuf[tid] = wpos[tid];
    __syncthreads();
    {
        int r = tid >> 2;
        int cs = (tid & 3) * 16;
        int gi = gIdx[g * GS + r];
        int pi = pIdx[g * GS + r];
        float4 p = *(const float4*)(pts + (size_t)pi * 4);
#pragma unroll
        for (int cc = 0; cc < 16; cc += 4) {
            int c = cs + cc;
            float4 f  = *(const float4*)(feats + (size_t)gi * 64 + c);
            float4 w0 = *(const float4*)(wbuf + c);
            float4 w1 = *(const float4*)(wbuf + 64 + c);
            float4 w2 = *(const float4*)(wbuf + 128 + c);
            float4 w3 = *(const float4*)(wbuf + 192 + c);
            f.x += p.x * w0.x + p.y * w1.x + p.z * w2.x + p.w * w3.x;
            f.y += p.x * w0.y + p.y * w1.y + p.z * w2.y + p.w * w3.y;
            f.z += p.x * w0.z + p.y * w1.z + p.z * w2.z + p.w * w3.z;
            f.w += p.x * w0.w + p.y * w1.w + p.z * w2.w + p.w * w3.w;
            *(float2*)(sx + r * SXS + c)     = make_float2(f.x, f.y);
            *(float2*)(sx + r * SXS + c + 2) = make_float2(f.z, f.w);
        }
    }
    __syncthreads();

    // ---- P1: ln -> sxn ----
    ln_rows(sx, sxn, tid);
    __syncthreads();

    // ---- P2: q/k/v via mma; weights in 32-krow chunks ----
    load_afrag(sxn, PAD, mrow, gid, tig, a0, a1);
#pragma unroll 1
    for (int s = 0; s < 3; s++) {
        float4 acc[4];
#pragma unroll
        for (int u = 0; u < 4; u++) acc[u] = make_float4(0.f, 0.f, 0.f, 0.f);
#pragma unroll 1
        for (int c = 0; c < 2; c++) {
            for (int i = tid; i < 2048; i += 256)
                wbuf[(i >> 6) * KVS + (i & 63)] =
                    tf32r(wqkv[(32 * c + (i >> 6)) * 192 + 64 * s + (i & 63)]);
            __syncthreads();
#pragma unroll
            for (int u = 0; u < 4; u++) {
                int nb = 8 * (wsel + 2 * u);
#pragma unroll
                for (int ks = 0; ks < 8; ks++)
                    mma4(acc[u], a0[8 * c + ks], a1[8 * c + ks],
                         wbuf[(4 * ks + tig) * KVS + nb + gid]);
            }
            __syncthreads();
        }
#pragma unroll
        for (int u = 0; u < 4; u++) {
            int n0 = 8 * (wsel + 2 * u) + 2 * tig, r0 = mrow + gid;
            if (s == 0) {          // q row-major into sxn (afrag already in regs)
                sxn[r0 * PAD + n0]           = tf32r(acc[u].x);
                sxn[r0 * PAD + n0 + 1]       = tf32r(acc[u].y);
                sxn[(r0 + 8) * PAD + n0]     = tf32r(acc[u].z);
                sxn[(r0 + 8) * PAD + n0 + 1] = tf32r(acc[u].w);
            } else if (s == 1) {   // k transposed [dim][key]
                skT[n0 * KVS + r0]           = tf32r(acc[u].x);
                skT[(n0 + 1) * KVS + r0]     = tf32r(acc[u].y);
                skT[n0 * KVS + r0 + 8]       = tf32r(acc[u].z);
                skT[(n0 + 1) * KVS + r0 + 8] = tf32r(acc[u].w);
            } else {               // v row-major [key][dim]
                sv[r0 * KVS + n0]           = tf32r(acc[u].x);
                sv[r0 * KVS + n0 + 1]       = tf32r(acc[u].y);
                sv[(r0 + 8) * KVS + n0]     = tf32r(acc[u].z);
                sv[(r0 + 8) * KVS + n0 + 1] = tf32r(acc[u].w);
            }
        }
    }
    __syncthreads();   // q,k,v complete

    // ---- P3: attention, head-pair passes p=0,1 (heads {2p,2p+1}) ----
    load_afrag(sxn, PAD, mrow, gid, tig, a0, a1);   // q frags (all 64 dims)
#pragma unroll 1
    for (int p = 0; p < 2; p++) {
        // scores -> satt (mma)
#pragma unroll
        for (int hh = 0; hh < 2; hh++) {
            int h = 2 * p + hh;
#pragma unroll
            for (int u = 0; u < 4; u++) {
                int nb = 8 * (wsel + 2 * u);
                float4 acc = make_float4(0.f, 0.f, 0.f, 0.f);
#pragma unroll
                for (int ks = 0; ks < 4; ks++)
                    mma4(acc, a0[4 * h + ks], a1[4 * h + ks],
                         skT[(16 * h + 4 * ks + tig) * KVS + nb + gid]);
                int r0 = mrow + gid, n0 = nb + 2 * tig;
                satt[(hh * 64 + r0) * PAD + n0]           = acc.x;
                satt[(hh * 64 + r0) * PAD + n0 + 1]       = acc.y;
                satt[(hh * 64 + r0 + 8) * PAD + n0]       = acc.z;
                satt[(hh * 64 + r0 + 8) * PAD + n0 + 1]   = acc.w;
            }
        }
        __syncthreads();
        // softmax (no max-subtract; scores O(1)), tf32 out
        {
            int row = tid >> 1, half = tid & 1;
            float* rp = satt + row * PAD + half * 32;
            float4 v4[8];
            float sum = 0.0f;
#pragma unroll
            for (int c = 0; c < 8; c++) {
                float4 f = *(float4*)(rp + 4 * c);
                f.x = __expf(f.x * 0.25f); f.y = __expf(f.y * 0.25f);
                f.z = __expf(f.z * 0.25f); f.w = __expf(f.w * 0.25f);
                sum += f.x + f.y + f.z + f.w;
                v4[c] = f;
            }
            sum += __shfl_xor_sync(0xffffffffu, sum, 1);
            float inv = 1.0f / sum;
#pragma unroll
            for (int c = 0; c < 8; c++) {
                *(float4*)(rp + 4 * c) = make_float4(
                    tf32r(v4[c].x * inv), tf32r(v4[c].y * inv),
                    tf32r(v4[c].z * inv), tf32r(v4[c].w * inv));
            }
        }
        __syncthreads();
        // AV -> o into sxn (mma); warp: hh=w&1, mr=16*(w>>1)
        {
            int hh = w & 1, mr = 16 * (w >> 1);
            int h = 2 * p + hh;
            float b0[16], b1[16];
            load_afrag(satt + hh * 64 * PAD, PAD, mr, gid, tig, b0, b1);
#pragma unroll
            for (int u = 0; u < 2; u++) {
                int nb = 8 * u;
                float4 acc = make_float4(0.f, 0.f, 0.f, 0.f);
#pragma unroll
                for (int ks = 0; ks < 16; ks++)
                    mma4(acc, b0[ks], b1[ks],
                         sv[(4 * ks + tig) * KVS + 16 * h + nb + gid]);
                int r0 = mr + gid, n0 = 16 * h + nb + 2 * tig;
                sxn[r0 * PAD + n0]           = tf32r(acc.x);
                sxn[r0 * PAD + n0 + 1]       = tf32r(acc.y);
                sxn[(r0 + 8) * PAD + n0]     = tf32r(acc.z);
                sxn[(r0 + 8) * PAD + n0 + 1] = tf32r(acc.w);
            }
        }
        __syncthreads();
    }

    // ---- P3c: x += o @ wo ----
    load_afrag(sxn, PAD, mrow, gid, tig, a0, a1);   // o frags
    {
        float4 acc[4];
#pragma unroll
        for (int u = 0; u < 4; u++) acc[u] = make_float4(0.f, 0.f, 0.f, 0.f);
#pragma unroll 1
        for (int c = 0; c < 2; c++) {
            for (int i = tid; i < 2048; i += 256)
                wbuf[(i >> 6) * KVS + (i & 63)] =
                    tf32r(wo[(32 * c + (i >> 6)) * 64 + (i & 63)]);
            __syncthreads();
#pragma unroll
            for (int u = 0; u < 4; u++) {
                int nb = 8 * (wsel + 2 * u);
#pragma unroll
                for (int ks = 0; ks < 8; ks++)
                    mma4(acc[u], a0[8 * c + ks], a1[8 * c + ks],
                         wbuf[(4 * ks + tig) * KVS + nb + gid]);
            }
            __syncthreads();
        }
#pragma unroll
        for (int u = 0; u < 4; u++) {
            int n0 = 8 * (wsel + 2 * u) + 2 * tig, r0 = mrow + gid;
            sx[r0 * SXS + n0]           += acc[u].x;
            sx[r0 * SXS + n0 + 1]       += acc[u].y;
            sx[(r0 + 8) * SXS + n0]     += acc[u].z;
            sx[(r0 + 8) * SXS + n0 + 1] += acc[u].w;
        }
    }
    __syncthreads();

    // ---- P4: FF in 4 quarters; accB persists ----
    ln_rows(sx, sxn, tid);
    float4 accB[4];
#pragma unroll
    for (int u = 0; u < 4; u++) accB[u] = make_float4(0.f, 0.f, 0.f, 0.f);

#pragma unroll 1
    for (int qtr = 0; qtr < 4; qtr++) {
        __syncthreads();   // sxn ready (qtr 0) / prev ffb mma done with wbuf
        load_afrag(sxn, PAD, mrow, gid, tig, a0, a1);
        float4 acc[4];
#pragma unroll
        for (int u = 0; u < 4; u++) acc[u] = make_float4(0.f, 0.f, 0.f, 0.f);
#pragma unroll 1
        for (int c = 0; c < 2; c++) {
            for (int i = tid; i < 2048; i += 256)
                wbuf[(i >> 6) * KVS + (i & 63)] =
                    tf32r(wffa[(32 * c + (i >> 6)) * 256 + 64 * qtr + (i & 63)]);
            __syncthreads();
#pragma unroll
            for (int u = 0; u < 4; u++) {
                int nb = 8 * (wsel + 2 * u);
#pragma unroll
                for (int ks = 0; ks < 8; ks++)
                    mma4(acc[u], a0[8 * c + ks], a1[8 * c + ks],
                         wbuf[(4 * ks + tig) * KVS + nb + gid]);
            }
            __syncthreads();
        }
#pragma unroll
        for (int u = 0; u < 4; u++) {
            int n0 = 8 * (wsel + 2 * u) + 2 * tig, r0 = mrow + gid;
            sh[r0 * PAD + n0]           = tf32r(gelu_tanh(acc[u].x));
            sh[r0 * PAD + n0 + 1]       = tf32r(gelu_tanh(acc[u].y));
            sh[(r0 + 8) * PAD + n0]     = tf32r(gelu_tanh(acc[u].z));
            sh[(r0 + 8) * PAD + n0 + 1] = tf32r(gelu_tanh(acc[u].w));
        }
        __syncthreads();
        load_afrag(sh, PAD, mrow, gid, tig, a0, a1);
#pragma unroll 1
        for (int c = 0; c < 2; c++) {
            __syncthreads();   // sh afrags loaded (c=0) / prev chunk mma done
            for (int i = tid; i < 2048; i += 256)
                wbuf[(i >> 6) * KVS + (i & 63)] =
                    tf32r(wffb[(64 * qtr + 32 * c + (i >> 6)) * 64 + (i & 63)]);
            __syncthreads();
#pragma unroll
            for (int u = 0; u < 4; u++) {
                int nb = 8 * (wsel + 2 * u);
#pragma unroll
                for (int ks = 0; ks < 8; ks++)
                    mma4(accB[u], a0[8 * c + ks], a1[8 * c + ks],
                         wbuf[(4 * ks + tig) * KVS + nb + gid]);
            }
        }
    }

    // ---- write out: dst = x + ff ----
#pragma unroll
    for (int u = 0; u < 4; u++) {
        int n0 = 8 * (wsel + 2 * u) + 2 * tig, r0 = mrow + gid;
        float2 lo = make_float2(sx[r0 * SXS + n0] + accB[u].x,
                                sx[r0 * SXS + n0 + 1] + accB[u].y);
        float2 hi = make_float2(sx[(r0 + 8) * SXS + n0] + accB[u].z,
                                sx[(r0 + 8) * SXS + n0 + 1] + accB[u].w);
        *(float2*)(dst + (size_t)(g * GS + r0) * 64 + n0)     = lo;
        *(float2*)(dst + (size_t)(g * GS + r0 + 8) * 64 + n0) = hi;
    }
}

// ---------------- launch ----------------
extern "C" void kernel_launch(void* const* d_in, const int* in_sizes, int n_in,
                              void* d_out, int out_size)
{
    const float* vox_feats = (const float*)d_in[0];
    const float* pts_coors = (const float*)d_in[1];
    const int*   vox_coors = (const int*)d_in[2];
    const float* w[10];
    for (int i = 0; i < 10; i++) w[i] = (const float*)d_in[n_in - 10 + i];
    float* out = (float*)d_out;

    cudaFuncSetAttribute(layer_kernel, cudaFuncAttributeMaxDynamicSharedMemorySize, SMEM_BYTES);

    codes_kernel<<<N_TOT / 256, 256>>>(vox_coors);

    dim3 gl(64, 2);
    bitonic_local_sort<<<gl, 1024>>>();
    for (int k = 8192; k <= N_TOT; k <<= 1) {
        for (int j = k >> 1; j >= 4096; j >>= 1)
            bitonic_global<<<dim3(512, 2), 256>>>(k, j);
        bitonic_local_merge<<<gl, 1024>>>(k);
    }

    extract_kernel<<<N_TOT / 256, 256>>>();
    ind12_kernel<<<N_TOT / 256, 256>>>();

    layer_kernel<<<NGRP, 256, SMEM_BYTES>>>(0, vox_feats, pts_coors,
                                            w[0], w[1], w[2], w[3], w[4], out);
    layer_kernel<<<NGRP, 256, SMEM_BYTES>>>(1, vox_feats, pts_coors,
                                            w[5], w[6], w[7], w[8], w[9], out);
}

// round 10
// speedup vs baseline: 2.2028x; 1.5550x over previous
#include <cuda_runtime.h>
#include <cuda_bf16.h>
#include <math.h>

typedef unsigned long long ull;

#define N_TOT 262144
#define GS    64
#define NGRP  (N_TOT / GS)

#define PAD 68   // sxn / satt / sh stride (A-frag friendly: ≡4 mod 32)
#define SXS 66   // sx stride (float2-only access)
#define KVS 72   // skT / sv / weight-chunk stride (B-operand friendly: ≡8 mod 32)
#define CHW 4608 // one weight chunk: 64 krows x 72

// ---------------- device scratch (no allocations allowed) ----------------
__device__ ull   g_keys[2][N_TOT];
__device__ int   g_ind1[N_TOT];
__device__ int   g_ind2[N_TOT];
__device__ int   g_inv1[N_TOT];
__device__ int   g_ind12[N_TOT];
__device__ float g_x1[(size_t)N_TOT * 64];
// tf32 pre-converted weights, 12 chunks of [64][72] per layer:
// 0-2 qkv(s), 3 wo, 4-7 ffa(qtr), 8-11 ffb(qtr)
__device__ float g_wtf[2][12 * CHW];

// ---------------- Hilbert encode (Skilling), order = 10 ----------------
__device__ __forceinline__ unsigned hilbert3(unsigned X0, unsigned X1, unsigned X2)
{
    const int order = 10;
    for (unsigned Q = 1u << (order - 1); Q > 1; Q >>= 1) {
        unsigned P = Q - 1;
        if (X0 & Q) X0 ^= P;
        unsigned t = (X0 ^ X1) & P;
        if (X1 & Q) { X0 ^= P; } else { X0 ^= t; X1 ^= t; }
        t = (X0 ^ X2) & P;
        if (X2 & Q) { X0 ^= P; } else { X0 ^= t; X2 ^= t; }
    }
    X1 ^= X0;
    X2 ^= X1;
    unsigned t = 0;
    for (unsigned Q = 1u << (order - 1); Q > 1; Q >>= 1)
        if (X2 & Q) t ^= (Q - 1);
    X0 ^= t; X1 ^= t; X2 ^= t;
    unsigned code = 0;
#pragma unroll
    for (int b = order - 1; b >= 0; b--) {
        code = (code << 3) | (((X0 >> b) & 1u) << 2) | (((X1 >> b) & 1u) << 1) | ((X2 >> b) & 1u);
    }
    return code;
}

__global__ void __launch_bounds__(256) codes_kernel(const int* __restrict__ vox_coors)
{
    int i = blockIdx.x * 256 + threadIdx.x;
    if (i >= N_TOT) return;
    int4 v = ((const int4*)vox_coors)[i];
    unsigned b  = (unsigned)v.x;
    unsigned c1 = hilbert3((unsigned)v.y, (unsigned)v.z,      (unsigned)v.w);
    unsigned c2 = hilbert3((unsigned)v.y, (unsigned)v.z + 1u, (unsigned)v.w + 1u);
    // Reference computes keys in int32 (JAX x64 disabled): batch<<30 overflows the
    // sign bit; signed ascending == unsigned ascending of (key ^ 0x80000000).
    unsigned k1 = (((b << 30) | c1) ^ 0x80000000u);
    unsigned k2 = (((b << 30) | c2) ^ 0x80000000u);
    g_keys[0][i] = (((ull)k1) << 32) | (unsigned)i;
    g_keys[1][i] = (((ull)k2) << 32) | (unsigned)i;
}

// ---------------- bitonic sort (uint64 ascending, N = 2^18) ----------------
__global__ void __launch_bounds__(1024) bitonic_local_sort()
{
    __shared__ ull s[4096];
    ull* arr = g_keys[blockIdx.y];
    int base = blockIdx.x * 4096;
    int tid = threadIdx.x;
#pragma unroll
    for (int e = 0; e < 4; e++) s[e * 1024 + tid] = arr[base + e * 1024 + tid];
    __syncthreads();
    for (int k = 2; k <= 4096; k <<= 1) {
        for (int j = k >> 1; j >= 1; j >>= 1) {
#pragma unroll
            for (int e = 0; e < 2; e++) {
                int v = e * 1024 + tid;
                int i = ((v & ~(j - 1)) << 1) | (v & (j - 1));
                int l = i | j;
                bool up = (((unsigned)(base + i)) & (unsigned)k) == 0;
                ull A = s[i], B = s[l];
                if ((A > B) == up) { s[i] = B; s[l] = A; }
            }
            __syncthreads();
        }
    }
#pragma unroll
    for (int e = 0; e < 4; e++) arr[base + e * 1024 + tid] = s[e * 1024 + tid];
}

__global__ void __launch_bounds__(1024) bitonic_local_merge(int k)
{
    __shared__ ull s[4096];
    ull* arr = g_keys[blockIdx.y];
    int base = blockIdx.x * 4096;
    int tid = threadIdx.x;
#pragma unroll
    for (int e = 0; e < 4; e++) s[e * 1024 + tid] = arr[base + e * 1024 + tid];
    __syncthreads();
    bool up = (((unsigned)base) & (unsigned)k) == 0;
    for (int j = 2048; j >= 1; j >>= 1) {
#pragma unroll
        for (int e = 0; e < 2; e++) {
            int v = e * 1024 + tid;
            int i = ((v & ~(j - 1)) << 1) | (v & (j - 1));
            int l = i | j;
            ull A = s[i], B = s[l];
            if ((A > B) == up) { s[i] = B; s[l] = A; }
        }
        __syncthreads();
    }
#pragma unroll
    for (int e = 0; e < 4; e++) arr[base + e * 1024 + tid] = s[e * 1024 + tid];
}

__global__ void __launch_bounds__(256) bitonic_global(int k, int j)
{
    ull* arr = g_keys[blockIdx.y];
    int v = blockIdx.x * 256 + threadIdx.x;
    int i = ((v & ~(j - 1)) << 1) | (v & (j - 1));
    int l = i | j;
    bool up = (((unsigned)i) & (unsigned)k) == 0;
    ull A = arr[i], B = arr[l];
    if ((A > B) == up) { arr[i] = B; arr[l] = A; }
}

__global__ void __launch_bounds__(256) extract_kernel()
{
    int i = blockIdx.x * 256 + threadIdx.x;
    int i1 = (int)(g_keys[0][i] & 0xffffffffull);
    int i2 = (int)(g_keys[1][i] & 0xffffffffull);
    g_ind1[i] = i1;
    g_ind2[i] = i2;
    g_inv1[i1] = i;
}

__global__ void __launch_bounds__(256) ind12_kernel()
{
    int i = blockIdx.x * 256 + threadIdx.x;
    g_ind12[i] = g_inv1[g_ind2[i]];
}

// ---------------- tf32 helpers ----------------
__device__ __forceinline__ float tf32r(float x)
{
    unsigned u;
    asm("cvt.rna.tf32.f32 %0, %1;" : "=r"(u) : "f"(x));
    return __uint_as_float(u);
}

// weight pre-convert: original layouts -> padded [64][72] tf32 chunks
__global__ void __launch_bounds__(256) wconv_kernel(
    int layer,
    const float* __restrict__ wqkv, const float* __restrict__ wo,
    const float* __restrict__ wffa, const float* __restrict__ wffb)
{
    int idx = blockIdx.x * 256 + threadIdx.x;
    if (idx >= 12 * CHW) return;
    int cid = idx / CHW;
    int rem = idx - cid * CHW;
    int r = rem / KVS, n = rem - r * KVS;
    float v = 0.0f;
    if (n < 64) {
        if (cid < 3)       v = wqkv[r * 192 + 64 * cid + n];
        else if (cid == 3) v = wo[r * 64 + n];
        else if (cid < 8)  v = wffa[r * 256 + 64 * (cid - 4) + n];
        else               v = wffb[(64 * (cid - 8) + r) * 64 + n];
    }
    g_wtf[layer][idx] = tf32r(v);
}

// m16n8k4 tf32 mma: D += A(16x4) * B(4x8).
// A: a0=(row g, col t), a1=(row g+8, col t); B: b0=(k t, col g);
// D: c0=(g,2t) c1=(g,2t+1) c2=(g+8,2t) c3=(g+8,2t+1).  (g=lane>>2, t=lane&3)
__device__ __forceinline__ void mma4(float4& d, float a0, float a1, float b0)
{
    asm volatile("mma.sync.aligned.m16n8k4.row.col.f32.tf32.tf32.f32 "
                 "{%0,%1,%2,%3}, {%4,%5}, {%6}, {%0,%1,%2,%3};"
                 : "+f"(d.x), "+f"(d.y), "+f"(d.z), "+f"(d.w)
                 : "r"(__float_as_uint(a0)), "r"(__float_as_uint(a1)),
                   "r"(__float_as_uint(b0)));
}

__device__ __forceinline__ void load_afrag(const float* A, int stride, int mrow,
                                           int gid, int tig, float* a0, float* a1)
{
#pragma unroll
    for (int ks = 0; ks < 16; ks++) {
        a0[ks] = A[(mrow + gid) * stride + 4 * ks + tig];
        a1[ks] = A[(mrow + gid + 8) * stride + 4 * ks + tig];
    }
}

__device__ __forceinline__ float gelu_tanh(float x)
{
    float x3 = x * x * x;
    float t = tanhf(0.7978845608028654f * (x + 0.044715f * x3));
    return 0.5f * x * (1.0f + t);
}

// layernorm rows: sx[64][SXS] -> tf32 sxn[64][PAD]  (8 warps x 8 rows)
__device__ __forceinline__ void ln_rows(const float* sx, float* sxn, int tid)
{
    int lane = tid & 31, w = tid >> 5;
#pragma unroll
    for (int rr = 0; rr < 8; rr++) {
        int r = w * 8 + rr;
        float a = sx[r * SXS + lane];
        float b = sx[r * SXS + lane + 32];
        float s = a + b, q = a * a + b * b;
#pragma unroll
        for (int m = 16; m; m >>= 1) {
            s += __shfl_xor_sync(0xffffffffu, s, m);
            q += __shfl_xor_sync(0xffffffffu, q, m);
        }
        float mean = s * (1.0f / 64.0f);
        float rs = rsqrtf(q * (1.0f / 64.0f) - mean * mean + 1e-5f);
        sxn[r * PAD + lane]      = tf32r((a - mean) * rs);
        sxn[r * PAD + lane + 32] = tf32r((b - mean) * rs);
    }
}

// smem: sx 64*66 | sxn 64*68 | skT 64*72 | sv 64*72 | satt 128*68
// weight chunks live in whichever region is dead: satt (qkv, wo), skT (ffa), sv (ffb)
#define SMEM_FLOATS (64*SXS + 64*PAD + 64*KVS + 64*KVS + 128*PAD)
#define SMEM_BYTES  (SMEM_FLOATS * 4)   // 105984 B -> 2 blocks/SM

__global__ void __launch_bounds__(256, 2) layer_kernel(
    int layer,
    const float* __restrict__ feats_in, const float* __restrict__ pts,
    const float* __restrict__ wpos, float* __restrict__ dst_out)
{
    extern __shared__ float smf[];
    float* sx   = smf;                  // [64][66] fp32 residual
    float* sxn  = sx   + 64 * SXS;      // [64][68] tf32 ln-out -> q -> o -> ln2
    float* skT  = sxn  + 64 * PAD;      // [64][72] kT [dim][key]  / ffa weights
    float* sv   = skT  + 64 * KVS;      // [64][72] v  [key][dim]  / ffb weights
    float* satt = sv   + 64 * KVS;      // [128][68] att / qkv+wo weights / sh
    float* sh   = satt;

    const float* wtf   = g_wtf[layer];
    const float* feats = layer ? g_x1   : feats_in;
    float*       dst   = layer ? dst_out : g_x1;
    const int*   gIdx  = layer ? g_ind12 : g_ind1;
    const int*   pIdx  = layer ? g_ind2  : g_ind1;

    int tid = threadIdx.x;
    int g = blockIdx.x;
    int lane = tid & 31, w = tid >> 5;
    int gid = lane >> 2, tig = lane & 3;
    int mrow = 16 * (w & 3), wsel = w >> 2;   // GEMM mapping: 4 M-tiles x 2 col-phases
    int hh2 = w & 1, mr2 = 16 * (w >> 1);     // attention mapping: 2 heads x 4 M-tiles

    float a0[16], a1[16];

    // ---- P0: stage wpos (into satt); x = feats[gIdx] + p @ wpos ----
    satt[tid] = wpos[tid];
    __syncthreads();
    {
        int r = tid >> 2;
        int cs = (tid & 3) * 16;
        int gi = gIdx[g * GS + r];
        int pi = pIdx[g * GS + r];
        float4 p = *(const float4*)(pts + (size_t)pi * 4);
#pragma unroll
        for (int cc = 0; cc < 16; cc += 4) {
            int c = cs + cc;
            float4 f  = *(const float4*)(feats + (size_t)gi * 64 + c);
            float4 w0 = *(const float4*)(satt + c);
            float4 w1 = *(const float4*)(satt + 64 + c);
            float4 w2 = *(const float4*)(satt + 128 + c);
            float4 w3 = *(const float4*)(satt + 192 + c);
            f.x += p.x * w0.x + p.y * w1.x + p.z * w2.x + p.w * w3.x;
            f.y += p.x * w0.y + p.y * w1.y + p.z * w2.y + p.w * w3.y;
            f.z += p.x * w0.z + p.y * w1.z + p.z * w2.z + p.w * w3.z;
            f.w += p.x * w0.w + p.y * w1.w + p.z * w2.w + p.w * w3.w;
            *(float2*)(sx + r * SXS + c)     = make_float2(f.x, f.y);
            *(float2*)(sx + r * SXS + c + 2) = make_float2(f.z, f.w);
        }
    }
    __syncthreads();

    // ---- P1: ln -> sxn ----
    ln_rows(sx, sxn, tid);
    __syncthreads();

    // ---- P2: q/k/v GEMMs; single 64-krow weight chunk in satt ----
    load_afrag(sxn, PAD, mrow, gid, tig, a0, a1);   // ln-out frags, persist across s
#pragma unroll 1
    for (int s = 0; s < 3; s++) {
        const float4* wsrc = (const float4*)(wtf + s * CHW);
        for (int i = tid; i < 1152; i += 256) ((float4*)satt)[i] = wsrc[i];
        __syncthreads();
        float4 acc[4];
#pragma unroll
        for (int u = 0; u < 4; u++) {
            acc[u] = make_float4(0.f, 0.f, 0.f, 0.f);
            int nb = 8 * (wsel + 2 * u);
#pragma unroll
            for (int ks = 0; ks < 16; ks++)
                mma4(acc[u], a0[ks], a1[ks], satt[(4 * ks + tig) * KVS + nb + gid]);
        }
#pragma unroll
        for (int u = 0; u < 4; u++) {
            int n0 = 8 * (wsel + 2 * u) + 2 * tig, r0 = mrow + gid;
            if (s == 0) {          // q row-major into sxn (ln frags already in regs)
                sxn[r0 * PAD + n0]           = tf32r(acc[u].x);
                sxn[r0 * PAD + n0 + 1]       = tf32r(acc[u].y);
                sxn[(r0 + 8) * PAD + n0]     = tf32r(acc[u].z);
                sxn[(r0 + 8) * PAD + n0 + 1] = tf32r(acc[u].w);
            } else if (s == 1) {   // k transposed [dim][key]
                skT[n0 * KVS + r0]           = tf32r(acc[u].x);
                skT[(n0 + 1) * KVS + r0]     = tf32r(acc[u].y);
                skT[n0 * KVS + r0 + 8]       = tf32r(acc[u].z);
                skT[(n0 + 1) * KVS + r0 + 8] = tf32r(acc[u].w);
            } else {               // v row-major [key][dim]
                sv[r0 * KVS + n0]           = tf32r(acc[u].x);
                sv[r0 * KVS + n0 + 1]       = tf32r(acc[u].y);
                sv[(r0 + 8) * KVS + n0]     = tf32r(acc[u].z);
                sv[(r0 + 8) * KVS + n0 + 1] = tf32r(acc[u].w);
            }
        }
        __syncthreads();
    }

    // ---- P3: attention; scores + in-register softmax fused, then AV ----
#pragma unroll 1
    for (int p = 0; p < 2; p++) {
        int h = 2 * p + hh2;
        float qa0[4], qa1[4];
#pragma unroll
        for (int ks = 0; ks < 4; ks++) {
            qa0[ks] = sxn[(mr2 + gid) * PAD + 16 * h + 4 * ks + tig];
            qa1[ks] = sxn[(mr2 + gid + 8) * PAD + 16 * h + 4 * ks + tig];
        }
        float4 sc[8];
#pragma unroll
        for (int u = 0; u < 8; u++) {
            sc[u] = make_float4(0.f, 0.f, 0.f, 0.f);
#pragma unroll
            for (int ks = 0; ks < 4; ks++)
                mma4(sc[u], qa0[ks], qa1[ks],
                     skT[(16 * h + 4 * ks + tig) * KVS + 8 * u + gid]);
        }
        float s0 = 0.0f, s1 = 0.0f;
#pragma unroll
        for (int u = 0; u < 8; u++) {
            sc[u].x = __expf(sc[u].x * 0.25f);  // 1/sqrt(16); scores O(1), no max needed
            sc[u].y = __expf(sc[u].y * 0.25f);
            sc[u].z = __expf(sc[u].z * 0.25f);
            sc[u].w = __expf(sc[u].w * 0.25f);
            s0 += sc[u].x + sc[u].y;
            s1 += sc[u].z + sc[u].w;
        }
        s0 += __shfl_xor_sync(0xffffffffu, s0, 1);
        s0 += __shfl_xor_sync(0xffffffffu, s0, 2);
        s1 += __shfl_xor_sync(0xffffffffu, s1, 1);
        s1 += __shfl_xor_sync(0xffffffffu, s1, 2);
        float i0 = 1.0f / s0, i1 = 1.0f / s1;
        int ar = hh2 * 64 + mr2 + gid;
#pragma unroll
        for (int u = 0; u < 8; u++) {
            int n0 = 8 * u + 2 * tig;
            satt[ar * PAD + n0]           = tf32r(sc[u].x * i0);
            satt[ar * PAD + n0 + 1]       = tf32r(sc[u].y * i0);
            satt[(ar + 8) * PAD + n0]     = tf32r(sc[u].z * i1);
            satt[(ar + 8) * PAD + n0 + 1] = tf32r(sc[u].w * i1);
        }
        __syncthreads();
        // AV: o = att @ v -> sxn cols [16h,16h+16)
        float b0f[16], b1f[16];
        load_afrag(satt + hh2 * 64 * PAD, PAD, mr2, gid, tig, b0f, b1f);
#pragma unroll
        for (int u = 0; u < 2; u++) {
            float4 acc = make_float4(0.f, 0.f, 0.f, 0.f);
#pragma unroll
            for (int ks = 0; ks < 16; ks++)
                mma4(acc, b0f[ks], b1f[ks],
                     sv[(4 * ks + tig) * KVS + 16 * h + 8 * u + gid]);
            int r0 = mr2 + gid, n0 = 16 * h + 8 * u + 2 * tig;
            sxn[r0 * PAD + n0]           = tf32r(acc.x);
            sxn[r0 * PAD + n0 + 1]       = tf32r(acc.y);
            sxn[(r0 + 8) * PAD + n0]     = tf32r(acc.z);
            sxn[(r0 + 8) * PAD + n0 + 1] = tf32r(acc.w);
        }
        __syncthreads();
    }

    // ---- P3c: x += o @ wo; also pre-stage ffa0 (skT) + ffb0 (sv) ----
    load_afrag(sxn, PAD, mrow, gid, tig, a0, a1);   // o frags
    {
        const float4* wo4 = (const float4*)(wtf + 3 * CHW);
        const float4* fa4 = (const float4*)(wtf + 4 * CHW);
        const float4* fb4 = (const float4*)(wtf + 8 * CHW);
        for (int i = tid; i < 1152; i += 256) {
            ((float4*)satt)[i] = wo4[i];
            ((float4*)skT)[i]  = fa4[i];
            ((float4*)sv)[i]   = fb4[i];
        }
    }
    __syncthreads();
    {
        float4 acc[4];
#pragma unroll
        for (int u = 0; u < 4; u++) {
            acc[u] = make_float4(0.f, 0.f, 0.f, 0.f);
            int nb = 8 * (wsel + 2 * u);
#pragma unroll
            for (int ks = 0; ks < 16; ks++)
                mma4(acc[u], a0[ks], a1[ks], satt[(4 * ks + tig) * KVS + nb + gid]);
        }
#pragma unroll
        for (int u = 0; u < 4; u++) {
            int n0 = 8 * (wsel + 2 * u) + 2 * tig, r0 = mrow + gid;
            sx[r0 * SXS + n0]           += acc[u].x;
            sx[r0 * SXS + n0 + 1]       += acc[u].y;
            sx[(r0 + 8) * SXS + n0]     += acc[u].z;
            sx[(r0 + 8) * SXS + n0 + 1] += acc[u].w;
        }
    }
    __syncthreads();

    // ---- P4: FF, 4 quarters, 2-phase pipeline (2 syncs each) ----
    ln_rows(sx, sxn, tid);
    __syncthreads();
    float4 accB[4];
#pragma unroll
    for (int u = 0; u < 4; u++) accB[u] = make_float4(0.f, 0.f, 0.f, 0.f);

#pragma unroll 1
    for (int qtr = 0; qtr < 4; qtr++) {
        // phase A: stage ffb(qtr) [qtr>0] || ffa mma -> gelu -> sh
        if (qtr > 0) {
            const float4* fb4 = (const float4*)(wtf + (8 + qtr) * CHW);
            for (int i = tid; i < 1152; i += 256) ((float4*)sv)[i] = fb4[i];
        }
        load_afrag(sxn, PAD, mrow, gid, tig, a0, a1);
        float4 acc[4];
#pragma unroll
        for (int u = 0; u < 4; u++) {
            acc[u] = make_float4(0.f, 0.f, 0.f, 0.f);
            int nb = 8 * (wsel + 2 * u);
#pragma unroll
            for (int ks = 0; ks < 16; ks++)
                mma4(acc[u], a0[ks], a1[ks], skT[(4 * ks + tig) * KVS + nb + gid]);
        }
#pragma unroll
        for (int u = 0; u < 4; u++) {
            int n0 = 8 * (wsel + 2 * u) + 2 * tig, r0 = mrow + gid;
            sh[r0 * PAD + n0]           = tf32r(gelu_tanh(acc[u].x));
            sh[r0 * PAD + n0 + 1]       = tf32r(gelu_tanh(acc[u].y));
            sh[(r0 + 8) * PAD + n0]     = tf32r(gelu_tanh(acc[u].z));
            sh[(r0 + 8) * PAD + n0 + 1] = tf32r(gelu_tanh(acc[u].w));
        }
        __syncthreads();
        // phase B: stage ffa(qtr+1) [qtr<3] || ffb mma -> accB
        if (qtr < 3) {
            const float4* fa4 = (const float4*)(wtf + (4 + qtr + 1) * CHW);
            for (int i = tid; i < 1152; i += 256) ((float4*)skT)[i] = fa4[i];
        }
        load_afrag(sh, PAD, mrow, gid, tig, a0, a1);
#pragma unroll
        for (int u = 0; u < 4; u++) {
            int nb = 8 * (wsel + 2 * u);
#pragma unroll
            for (int ks = 0; ks < 16; ks++)
                mma4(accB[u], a0[ks], a1[ks], sv[(4 * ks + tig) * KVS + nb + gid]);
        }
        __syncthreads();
    }

    // ---- write out: dst = x + ff ----
#pragma unroll
    for (int u = 0; u < 4; u++) {
        int n0 = 8 * (wsel + 2 * u) + 2 * tig, r0 = mrow + gid;
        float2 lo = make_float2(sx[r0 * SXS + n0] + accB[u].x,
                                sx[r0 * SXS + n0 + 1] + accB[u].y);
        float2 hi = make_float2(sx[(r0 + 8) * SXS + n0] + accB[u].z,
                                sx[(r0 + 8) * SXS + n0 + 1] + accB[u].w);
        *(float2*)(dst + (size_t)(g * GS + r0) * 64 + n0)     = lo;
        *(float2*)(dst + (size_t)(g * GS + r0 + 8) * 64 + n0) = hi;
    }
}

// ---------------- launch ----------------
extern "C" void kernel_launch(void* const* d_in, const int* in_sizes, int n_in,
                              void* d_out, int out_size)
{
    const float* vox_feats = (const float*)d_in[0];
    const float* pts_coors = (const float*)d_in[1];
    const int*   vox_coors = (const int*)d_in[2];
    const float* w[10];
    for (int i = 0; i < 10; i++) w[i] = (const float*)d_in[n_in - 10 + i];
    float* out = (float*)d_out;

    cudaFuncSetAttribute(layer_kernel, cudaFuncAttributeMaxDynamicSharedMemorySize, SMEM_BYTES);

    codes_kernel<<<N_TOT / 256, 256>>>(vox_coors);
    wconv_kernel<<<(12 * CHW + 255) / 256, 256>>>(0, w[1], w[2], w[3], w[4]);
    wconv_kernel<<<(12 * CHW + 255) / 256, 256>>>(1, w[6], w[7], w[8], w[9]);

    dim3 gl(64, 2);
    bitonic_local_sort<<<gl, 1024>>>();
    for (int k = 8192; k <= N_TOT; k <<= 1) {
        for (int j = k >> 1; j >= 4096; j >>= 1)
            bitonic_global<<<dim3(512, 2), 256>>>(k, j);
        bitonic_local_merge<<<gl, 1024>>>(k);
    }

    extract_kernel<<<N_TOT / 256, 256>>>();
    ind12_kernel<<<N_TOT / 256, 256>>>();

    layer_kernel<<<NGRP, 256, SMEM_BYTES>>>(0, vox_feats, pts_coors, w[0], out);
    layer_kernel<<<NGRP, 256, SMEM_BYTES>>>(1, vox_feats, pts_coors, w[5], out);
}